// round 15
// baseline (speedup 1.0000x reference)
#include <cuda_runtime.h>
#include <cuda_bf16.h>
#include <cuda_fp16.h>
#include <math.h>
#include <stdint.h>
#include <stddef.h>

// Problem constants
constexpr int B   = 2;
constexpr int T   = 768;
constexpr int KV  = 256;
constexpr int S   = 1024;
constexpr int D   = 1024;
constexpr int H   = 16;
constexpr int DH  = 64;
constexpr int L   = 6;
constexpr int V   = 32000;
constexpr int NTOK = B * S;
constexpr int PHYS_TOK = 5;

// ---------------- fp32 scratch ----------------------------------------------
__device__ float g_x  [NTOK * D];
__device__ int   g_pe [B];

// ---------------- fp16 storage ------------------------------------------------
__device__ __half w_qkv[L*3*D*D];
__device__ __half w_out[L*D*D];
__device__ __half w_ff1[L*4*D*D];
__device__ __half w_ff2[L*4*D*D];
__device__ __half w_te [(size_t)V*D];
__device__ __half a_h [NTOK*D],   a_l [NTOK*D];
__device__ __half a2_h[NTOK*4*D], a2_l[NTOK*4*D];
__device__ __half qkv_h[NTOK*3*D], qkv_l[NTOK*3*D];

// ============================ PTX helpers ====================================
__device__ __forceinline__ uint32_t smem_to_u32(const void* p) {
    uint32_t a;
    asm("{ .reg .u64 t; cvta.to.shared.u64 t, %1; cvt.u32.u64 %0, t; }" : "=r"(a) : "l"(p));
    return a;
}
__device__ __forceinline__ void ldmx4(uint32_t* r, uint32_t addr) {
    asm volatile("ldmatrix.sync.aligned.m8n8.x4.shared.b16 {%0,%1,%2,%3}, [%4];"
        : "=r"(r[0]), "=r"(r[1]), "=r"(r[2]), "=r"(r[3]) : "r"(addr));
}
__device__ __forceinline__ void ldmx4t(uint32_t* r, uint32_t addr) {
    asm volatile("ldmatrix.sync.aligned.m8n8.x4.trans.shared.b16 {%0,%1,%2,%3}, [%4];"
        : "=r"(r[0]), "=r"(r[1]), "=r"(r[2]), "=r"(r[3]) : "r"(addr));
}
__device__ __forceinline__ void mma_fp16(float* c, const uint32_t* a, const uint32_t* b) {
    asm volatile("mma.sync.aligned.m16n8k16.row.col.f32.f16.f16.f32 "
        "{%0,%1,%2,%3}, {%4,%5,%6,%7}, {%8,%9}, {%0,%1,%2,%3};"
        : "+f"(c[0]), "+f"(c[1]), "+f"(c[2]), "+f"(c[3])
        : "r"(a[0]), "r"(a[1]), "r"(a[2]), "r"(a[3]), "r"(b[0]), "r"(b[1]));
}
__device__ __forceinline__ void cp16(uint32_t dst, const void* src) {
    asm volatile("cp.async.cg.shared.global [%0], [%1], 16;" :: "r"(dst), "l"(src));
}
__device__ __forceinline__ void cp_commit() {
    asm volatile("cp.async.commit_group;" ::: "memory");
}
template<int N>
__device__ __forceinline__ void cp_wait() {
    asm volatile("cp.async.wait_group %0;" :: "n"(N) : "memory");
}
__device__ __forceinline__ uint32_t pack_h2(float a, float b) {
    __half2 t;
    t.x = __float2half_rn(a); t.y = __float2half_rn(b);
    return *(uint32_t*)&t;
}

// ---------------- small kernels ----------------------------------------------
// parallel first-PHYS_TOK scan: grid B, block T threads
__global__ void pe_kernel(const int* __restrict__ idx) {
    __shared__ int mn;
    if (threadIdx.x == 0) mn = T;
    __syncthreads();
    int b = blockIdx.x;
    if (idx[b * T + threadIdx.x] == PHYS_TOK) atomicMin(&mn, (int)threadIdx.x);
    __syncthreads();
    if (threadIdx.x == 0) g_pe[b] = (mn < T) ? mn + 1 : 0;
}

// vectorized embedding splice (4 elems per thread)
__global__ void embed_kernel(const int* __restrict__ idx, const float* __restrict__ vis,
                             const float* __restrict__ wte, const float* __restrict__ wpe) {
    int i4 = blockIdx.x * blockDim.x + threadIdx.x;   // over NTOK*D/4
    int e = i4 * 4;
    int d = e & (D - 1);
    int p = (e / D) & (S - 1);
    int b = e / (D * S);
    int pe = g_pe[b];
    float4 v;
    if (p >= pe && p < pe + KV) {
        v = *(const float4*)(vis + ((size_t)b * KV + (p - pe)) * D + d);
    } else {
        int ti = (p < pe) ? p : (p - KV);
        ti = min(max(ti, 0), T - 1);
        v = *(const float4*)(wte + (size_t)idx[b * T + ti] * D + d);
    }
    float4 w = *(const float4*)(wpe + (size_t)p * D + d);
    v.x += w.x; v.y += w.y; v.z += w.z; v.w += w.w;
    *(float4*)(g_x + e) = v;
}

// LayerNorm with fused fp16 hi/lo split output (vectorized)
__global__ void ln_split_kernel(const float* __restrict__ in,
                                const float* __restrict__ w, const float* __restrict__ b,
                                __half* __restrict__ oh, __half* __restrict__ ol) {
    int row = blockIdx.x;
    const float* x = in + (size_t)row * D;
    int j0 = threadIdx.x * 4;
    float4 xv = *(const float4*)(x + j0);
    float s  = xv.x + xv.y + xv.z + xv.w;
    float s2 = xv.x * xv.x + xv.y * xv.y + xv.z * xv.z + xv.w * xv.w;
#pragma unroll
    for (int o = 16; o; o >>= 1) { s += __shfl_xor_sync(~0u, s, o); s2 += __shfl_xor_sync(~0u, s2, o); }
    __shared__ float sh1[8], sh2[8];
    int wid = threadIdx.x >> 5, lid = threadIdx.x & 31;
    if (lid == 0) { sh1[wid] = s; sh2[wid] = s2; }
    __syncthreads();
    s = 0.f; s2 = 0.f;
#pragma unroll
    for (int wg = 0; wg < 8; wg++) { s += sh1[wg]; s2 += sh2[wg]; }
    float mean = s * (1.f / D);
    float var  = s2 * (1.f / D) - mean * mean;
    float inv  = rsqrtf(var + 1e-5f);
    float4 wv = *(const float4*)(w + j0);
    float4 bv = *(const float4*)(b + j0);
    float y0 = (xv.x - mean) * inv * wv.x + bv.x;
    float y1 = (xv.y - mean) * inv * wv.y + bv.y;
    float y2 = (xv.z - mean) * inv * wv.z + bv.z;
    float y3 = (xv.w - mean) * inv * wv.w + bv.w;
    __half2 h01, h23, l01, l23;
    h01.x = __float2half_rn(y0); h01.y = __float2half_rn(y1);
    h23.x = __float2half_rn(y2); h23.y = __float2half_rn(y3);
    l01.x = __float2half_rn(y0 - __half2float(h01.x));
    l01.y = __float2half_rn(y1 - __half2float(h01.y));
    l23.x = __float2half_rn(y2 - __half2float(h23.x));
    l23.y = __float2half_rn(y3 - __half2float(h23.y));
    *(__half2*)(oh + (size_t)row * D + j0)     = h01;
    *(__half2*)(oh + (size_t)row * D + j0 + 2) = h23;
    *(__half2*)(ol + (size_t)row * D + j0)     = l01;
    *(__half2*)(ol + (size_t)row * D + j0 + 2) = l23;
}

// fp32 -> fp16 weight convert: grid-stride, small grid (background sponge)
__global__ void cvt_kernel(const float4* __restrict__ x, __half2* __restrict__ o, int n4) {
    for (int i = blockIdx.x * blockDim.x + threadIdx.x; i < n4; i += gridDim.x * blockDim.x) {
        float4 v = x[i];
        __half2 h0, h1;
        h0.x = __float2half_rn(v.x); h0.y = __float2half_rn(v.y);
        h1.x = __float2half_rn(v.z); h1.y = __float2half_rn(v.w);
        o[i * 2]     = h0;
        o[i * 2 + 1] = h1;
    }
}

__device__ __forceinline__ float gelu_exact(float x) {
    return 0.5f * x * (1.f + erff(x * 0.70710678118654752f));
}

// ================= fp16 GEMM (split A optional, single W), 3-stage pipeline ==
constexpr int LDSROW = 40;
constexpr int TILE_BYTES = 128 * LDSROW * 2;
constexpr int BUF_BYTES  = 3 * TILE_BYTES;
constexpr int GEMM_SMEM  = 3 * BUF_BYTES;

__device__ __forceinline__ void cp_tile(uint32_t dst, const __half* __restrict__ src,
                                        int Kd, int k0) {
    int tid = threadIdx.x;
#pragma unroll
    for (int i = 0; i < 2; i++) {
        int v = tid * 2 + i;
        int row = v >> 2, seg = v & 3;
        cp16(dst + (uint32_t)(row * LDSROW + seg * 8) * 2,
             src + (size_t)row * Kd + k0 + seg * 8);
    }
}

template<bool BIAS, bool GELU, bool RES, bool SPLIT, bool TWOTERM>
__global__ __launch_bounds__(256, 2)
void gemm_mma(const __half* __restrict__ A1, const __half* __restrict__ A0,
              const __half* __restrict__ W,
              const float* __restrict__ bias, const float* __restrict__ res,
              float* __restrict__ C, __half* __restrict__ Ch,
              __half* __restrict__ Cl, int N, int Kd) {
    extern __shared__ char smem[];
    const uint32_t sbase = smem_to_u32(smem);

    const int tid  = threadIdx.x;
    const int lane = tid & 31;
    const int wid  = tid >> 5;
    const int wm   = wid >> 1;
    const int wn   = wid & 1;
    const int bm   = blockIdx.x * 128;
    const int bn   = blockIdx.y * 128;

    const __half* pA1 = A1 + (size_t)bm * Kd;
    const __half* pA0 = A0 + (size_t)bm * Kd;
    const __half* pW  = W  + (size_t)bn * Kd;

    const uint32_t frag_lane = (uint32_t)((lane & 15) * LDSROW + (lane >> 4) * 8);
    const int nch = Kd / 32;

    auto issue = [&](int ch) {
        uint32_t b = sbase + (uint32_t)(ch % 3) * BUF_BYTES;
        int k0 = ch * 32;
        cp_tile(b,                  pA1, Kd, k0);
        if (TWOTERM) cp_tile(b + TILE_BYTES, pA0, Kd, k0);
        cp_tile(b + 2 * TILE_BYTES, pW,  Kd, k0);
        cp_commit();
    };

    float c[2][8][4];
#pragma unroll
    for (int mt = 0; mt < 2; mt++)
#pragma unroll
        for (int nt = 0; nt < 8; nt++)
#pragma unroll
            for (int q = 0; q < 4; q++) c[mt][nt][q] = 0.f;

    issue(0);
    issue(1);

    for (int ch = 0; ch < nch; ch++) {
        if (ch < nch - 1) cp_wait<1>(); else cp_wait<0>();
        __syncthreads();
        if (ch + 2 < nch) issue(ch + 2);
        uint32_t b = sbase + (uint32_t)(ch % 3) * BUF_BYTES;
#pragma unroll
        for (int ks = 0; ks < 2; ks++) {
            uint32_t a1f[2][4], a0f[2][4];
#pragma unroll
            for (int mt = 0; mt < 2; mt++) {
                uint32_t off = ((uint32_t)((wm * 32 + mt * 16) * LDSROW + ks * 16) + frag_lane) * 2;
                ldmx4(a1f[mt], b + off);
                if (TWOTERM) ldmx4(a0f[mt], b + TILE_BYTES + off);
            }
            uint32_t wf[8][2];
#pragma unroll
            for (int jj = 0; jj < 4; jj++) {
                uint32_t off = ((uint32_t)((wn * 64 + jj * 16) * LDSROW + ks * 16) + frag_lane) * 2;
                uint32_t t[4];
                ldmx4(t, b + 2 * TILE_BYTES + off);
                wf[jj * 2][0]     = t[0]; wf[jj * 2 + 1][0] = t[1];
                wf[jj * 2][1]     = t[2]; wf[jj * 2 + 1][1] = t[3];
            }
#pragma unroll
            for (int mt = 0; mt < 2; mt++)
#pragma unroll
                for (int nt = 0; nt < 8; nt++) {
                    mma_fp16(c[mt][nt], a1f[mt], wf[nt]);
                    if (TWOTERM) mma_fp16(c[mt][nt], a0f[mt], wf[nt]);
                }
        }
    }

    const int row0 = bm + wm * 32;
    const int col0 = bn + wn * 64;
#pragma unroll
    for (int mt = 0; mt < 2; mt++) {
#pragma unroll
        for (int nt = 0; nt < 8; nt++) {
            int r  = row0 + mt * 16 + (lane >> 2);
            int cl = col0 + nt * 8 + (lane & 3) * 2;
#pragma unroll
            for (int half = 0; half < 2; half++) {
                int rr = r + half * 8;
                float v0 = c[mt][nt][half * 2];
                float v1 = c[mt][nt][half * 2 + 1];
                if (BIAS) { v0 += bias[cl]; v1 += bias[cl + 1]; }
                if (GELU) { v0 = gelu_exact(v0); v1 = gelu_exact(v1); }
                if (RES) {
                    const float* rp = res + (size_t)rr * N + cl;
                    v0 += rp[0]; v1 += rp[1];
                }
                if (SPLIT) {
                    __half2 hh, ll;
                    hh.x = __float2half_rn(v0);
                    hh.y = __float2half_rn(v1);
                    ll.x = __float2half_rn(v0 - __half2float(hh.x));
                    ll.y = __float2half_rn(v1 - __half2float(hh.y));
                    *(__half2*)(Ch + (size_t)rr * N + cl) = hh;
                    *(__half2*)(Cl + (size_t)rr * N + cl) = ll;
                } else {
                    *(float2*)(C + (size_t)rr * N + cl) = make_float2(v0, v1);
                }
            }
        }
    }
}

// ================= fused flash attention (fp16 split, 3-stage pipeline) ======
constexpr int QROW = 72;
constexpr int KVBUF_ELEM = 4 * 64 * QROW;
constexpr int FLASH_SMEM = (2 * 128 * QROW + 3 * KVBUF_ELEM) * 2;

__global__ __launch_bounds__(256, 1)
void flash_kernel(const __half* __restrict__ qg_h, const __half* __restrict__ qg_l,
                  __half* __restrict__ oh, __half* __restrict__ ol) {
    extern __shared__ char smemc[];
    __half* smem = (__half*)smemc;
    __half* sQh = smem;
    __half* sQl = sQh + 128 * QROW;
    __half* sKV = sQl + 128 * QROW;

    const int tid = threadIdx.x, lane = tid & 31, w = tid >> 5;
    const int bh = blockIdx.y, b = bh >> 4, h = bh & 15;
    const int qBase = blockIdx.x * 128;
    const int pe = g_pe[b], ve = pe + KV;

    const uint32_t aQh = smem_to_u32(sQh), aQl = smem_to_u32(sQl);
    const uint32_t aKV = smem_to_u32(sKV);

    const int kEnd = min(S, max(qBase + 128, ve));
    const int nk = (kEnd + 63) >> 6;

    auto issue_kv = [&](int t) {
        uint32_t base = aKV + (uint32_t)(t % 3) * (KVBUF_ELEM * 2);
        int k0 = t * 64;
#pragma unroll
        for (int it = 0; it < 8; it++) {
            int c = it * 256 + tid;
            int comp = c >> 9;
            int r    = (c >> 3) & 63;
            int seg  = c & 7;
            const __half* src = ((comp & 1) ? qg_l : qg_h)
                + (size_t)(b * S + k0 + r) * (3 * D) + ((comp < 2) ? D : 2 * D) + h * DH + seg * 8;
            cp16(base + (uint32_t)(comp * 64 * QROW + r * QROW + seg * 8) * 2, src);
        }
        cp_commit();
    };

#pragma unroll
    for (int it = 0; it < 8; it++) {
        int c = it * 256 + tid;
        int hl  = c >> 10;
        int r   = (c >> 3) & 127;
        int seg = c & 7;
        const __half* src = (hl ? qg_l : qg_h)
            + (size_t)(b * S + qBase + r) * (3 * D) + h * DH + seg * 8;
        cp16((hl ? aQl : aQh) + (uint32_t)(r * QROW + seg * 8) * 2, src);
    }
    issue_kv(0);
    issue_kv(1);

    const uint32_t flq = (uint32_t)((lane & 15) * QROW + (lane >> 4) * 8);
    const uint32_t flv = (uint32_t)(((lane & 7) + ((lane >> 3) & 1) * 8) * QROW + (lane >> 4) * 8);

    uint32_t qh[4][4], ql[4][4];
    float acc[8][4];
#pragma unroll
    for (int nt = 0; nt < 8; nt++)
#pragma unroll
        for (int e = 0; e < 4; e++) acc[nt][e] = 0.f;
    float m0 = -1e30f, m1 = -1e30f, l0 = 0.f, l1 = 0.f;
    const int qr = qBase + w * 16 + (lane >> 2);

    for (int i = 0; i < nk; i++) {
        if (i < nk - 1) cp_wait<1>(); else cp_wait<0>();
        __syncthreads();
        if (i + 2 < nk) issue_kv(i + 2);

        if (i == 0) {
#pragma unroll
            for (int kk = 0; kk < 4; kk++) {
                uint32_t off = ((uint32_t)(w * 16 * QROW + kk * 16) + flq) * 2;
                ldmx4(qh[kk], aQh + off);
                ldmx4(ql[kk], aQl + off);
            }
        }

        uint32_t base = aKV + (uint32_t)(i % 3) * (KVBUF_ELEM * 2);
        const uint32_t bKh = base;
        const uint32_t bKl = base + 64 * QROW * 2;
        const uint32_t bVh = base + 2 * 64 * QROW * 2;
        const uint32_t bVl = base + 3 * 64 * QROW * 2;
        int k0 = i * 64;

        float c[8][4];
#pragma unroll
        for (int nt = 0; nt < 8; nt++)
#pragma unroll
            for (int e = 0; e < 4; e++) c[nt][e] = 0.f;
#pragma unroll
        for (int kk = 0; kk < 4; kk++) {
#pragma unroll
            for (int jj = 0; jj < 4; jj++) {
                uint32_t off = ((uint32_t)((jj * 16) * QROW + kk * 16) + flq) * 2;
                uint32_t th[4], tl[4];
                ldmx4(th, bKh + off);
                ldmx4(tl, bKl + off);
                uint32_t kh0[2] = { th[0], th[2] }, kh1[2] = { th[1], th[3] };
                uint32_t kl0[2] = { tl[0], tl[2] }, kl1[2] = { tl[1], tl[3] };
                mma_fp16(c[jj * 2],     qh[kk], kh0);
                mma_fp16(c[jj * 2],     qh[kk], kl0);
                mma_fp16(c[jj * 2],     ql[kk], kh0);
                mma_fp16(c[jj * 2 + 1], qh[kk], kh1);
                mma_fp16(c[jj * 2 + 1], qh[kk], kl1);
                mma_fp16(c[jj * 2 + 1], ql[kk], kh1);
            }
        }

        float mx0 = -1e30f, mx1 = -1e30f;
#pragma unroll
        for (int nt = 0; nt < 8; nt++) {
            int kc = k0 + nt * 8 + (lane & 3) * 2;
#pragma unroll
            for (int e = 0; e < 4; e++) {
                int q = qr + ((e >= 2) ? 8 : 0);
                int k = kc + (e & 1);
                bool allowed = (q < pe && k < pe) ||
                               (q >= pe && q < ve && k < ve) ||
                               (q >= ve && k <= q);
                float s = allowed ? c[nt][e] * 0.125f : -1e9f;
                c[nt][e] = s;
                if (e < 2) mx0 = fmaxf(mx0, s); else mx1 = fmaxf(mx1, s);
            }
        }
        mx0 = fmaxf(mx0, __shfl_xor_sync(~0u, mx0, 1));
        mx0 = fmaxf(mx0, __shfl_xor_sync(~0u, mx0, 2));
        mx1 = fmaxf(mx1, __shfl_xor_sync(~0u, mx1, 1));
        mx1 = fmaxf(mx1, __shfl_xor_sync(~0u, mx1, 2));

        float mn0 = fmaxf(m0, mx0), mn1 = fmaxf(m1, mx1);
        float al0 = __expf(m0 - mn0), al1 = __expf(m1 - mn1);
        m0 = mn0; m1 = mn1;

        uint32_t ph[4][4], pl[4][4];
        float rs0 = 0.f, rs1 = 0.f;
#pragma unroll
        for (int nt = 0; nt < 8; nt++) {
            float p0 = __expf(c[nt][0] - m0);
            float p1 = __expf(c[nt][1] - m0);
            float p2 = __expf(c[nt][2] - m1);
            float p3 = __expf(c[nt][3] - m1);
            rs0 += p0 + p1; rs1 += p2 + p3;
            __half h0 = __float2half_rn(p0), h1 = __float2half_rn(p1);
            __half h2 = __float2half_rn(p2), h3 = __float2half_rn(p3);
            int ck = nt >> 1, ps = (nt & 1) * 2;
            __half2 t;
            t.x = h0; t.y = h1; ph[ck][ps]     = *(uint32_t*)&t;
            t.x = h2; t.y = h3; ph[ck][ps + 1] = *(uint32_t*)&t;
            pl[ck][ps]     = pack_h2(p0 - __half2float(h0), p1 - __half2float(h1));
            pl[ck][ps + 1] = pack_h2(p2 - __half2float(h2), p3 - __half2float(h3));
        }
        rs0 += __shfl_xor_sync(~0u, rs0, 1); rs0 += __shfl_xor_sync(~0u, rs0, 2);
        rs1 += __shfl_xor_sync(~0u, rs1, 1); rs1 += __shfl_xor_sync(~0u, rs1, 2);
        l0 = l0 * al0 + rs0;
        l1 = l1 * al1 + rs1;

#pragma unroll
        for (int nt = 0; nt < 8; nt++) {
            acc[nt][0] *= al0; acc[nt][1] *= al0;
            acc[nt][2] *= al1; acc[nt][3] *= al1;
        }

#pragma unroll
        for (int kk = 0; kk < 4; kk++) {
#pragma unroll
            for (int jj = 0; jj < 4; jj++) {
                uint32_t off = ((uint32_t)(kk * 16 * QROW + jj * 16) + flv) * 2;
                uint32_t th[4], tl[4];
                ldmx4t(th, bVh + off);
                ldmx4t(tl, bVl + off);
                uint32_t vh0[2] = { th[0], th[1] }, vh1[2] = { th[2], th[3] };
                uint32_t vl0[2] = { tl[0], tl[1] }, vl1[2] = { tl[2], tl[3] };
                mma_fp16(acc[jj * 2],     ph[kk], vh0);
                mma_fp16(acc[jj * 2],     ph[kk], vl0);
                mma_fp16(acc[jj * 2],     pl[kk], vh0);
                mma_fp16(acc[jj * 2 + 1], ph[kk], vh1);
                mma_fp16(acc[jj * 2 + 1], ph[kk], vl1);
                mma_fp16(acc[jj * 2 + 1], pl[kk], vh1);
            }
        }
    }

    const float il0 = 1.f / l0, il1 = 1.f / l1;
#pragma unroll
    for (int nt = 0; nt < 8; nt++) {
        int dcol = h * DH + nt * 8 + (lane & 3) * 2;
        size_t o0 = (size_t)(b * S + qr) * D + dcol;
        size_t o1 = (size_t)(b * S + qr + 8) * D + dcol;
        float v0 = acc[nt][0] * il0, v1 = acc[nt][1] * il0;
        float v2 = acc[nt][2] * il1, v3 = acc[nt][3] * il1;
        __half2 hh, ll;
        hh.x = __float2half_rn(v0); hh.y = __float2half_rn(v1);
        ll.x = __float2half_rn(v0 - __half2float(hh.x));
        ll.y = __float2half_rn(v1 - __half2float(hh.y));
        *(__half2*)(oh + o0) = hh;
        *(__half2*)(ol + o0) = ll;
        hh.x = __float2half_rn(v2); hh.y = __float2half_rn(v3);
        ll.x = __float2half_rn(v2 - __half2float(hh.x));
        ll.y = __float2half_rn(v3 - __half2float(hh.y));
        *(__half2*)(oh + o1) = hh;
        *(__half2*)(ol + o1) = ll;
    }
}

// ---------------- host: launch sequence --------------------------------------
static inline void cvt_on(cudaStream_t s, const float* x, __half* o, size_t n) {
    int n4 = (int)(n / 4);
    cvt_kernel<<<120, 256, 0, s>>>((const float4*)x, (__half2*)o, n4);  // background sponge
}

extern "C" void kernel_launch(void* const* d_in, const int* in_sizes, int n_in,
                              void* d_out, int out_size) {
    const int*   idx    = (const int*)  d_in[0];
    const float* vis    = (const float*)d_in[1];
    const float* wte    = (const float*)d_in[2];
    const float* wpe    = (const float*)d_in[3];
    const float* qkv_w  = (const float*)d_in[4];
    const float* qkv_b  = (const float*)d_in[5];
    const float* out_w  = (const float*)d_in[6];
    const float* out_b  = (const float*)d_in[7];
    const float* ln1_w  = (const float*)d_in[8];
    const float* ln1_b  = (const float*)d_in[9];
    const float* ln2_w  = (const float*)d_in[10];
    const float* ln2_b  = (const float*)d_in[11];
    const float* ff1_w  = (const float*)d_in[12];
    const float* ff1_b  = (const float*)d_in[13];
    const float* ff2_w  = (const float*)d_in[14];
    const float* ff2_b  = (const float*)d_in[15];
    const float* lnf_w  = (const float*)d_in[16];
    const float* lnf_b  = (const float*)d_in[17];
    float* logits = (float*)d_out;

    cudaFuncSetAttribute(gemm_mma<true,  false, false, true,  true >, cudaFuncAttributeMaxDynamicSharedMemorySize, GEMM_SMEM);
    cudaFuncSetAttribute(gemm_mma<true,  false, true,  false, true >, cudaFuncAttributeMaxDynamicSharedMemorySize, GEMM_SMEM);
    cudaFuncSetAttribute(gemm_mma<true,  true,  false, true,  true >, cudaFuncAttributeMaxDynamicSharedMemorySize, GEMM_SMEM);
    cudaFuncSetAttribute(gemm_mma<false, false, false, false, false>, cudaFuncAttributeMaxDynamicSharedMemorySize, GEMM_SMEM);
    cudaFuncSetAttribute(flash_kernel, cudaFuncAttributeMaxDynamicSharedMemorySize, FLASH_SMEM);

    float* px;
    cudaGetSymbolAddress((void**)&px, g_x);
    __half *pah, *pal, *pa2h, *pa2l, *pqh, *pql, *pwq, *pwo, *pf1, *pf2, *pte;
    cudaGetSymbolAddress((void**)&pah,  a_h);
    cudaGetSymbolAddress((void**)&pal,  a_l);
    cudaGetSymbolAddress((void**)&pa2h, a2_h);
    cudaGetSymbolAddress((void**)&pa2l, a2_l);
    cudaGetSymbolAddress((void**)&pqh,  qkv_h);
    cudaGetSymbolAddress((void**)&pql,  qkv_l);
    cudaGetSymbolAddress((void**)&pwq,  w_qkv);
    cudaGetSymbolAddress((void**)&pwo,  w_out);
    cudaGetSymbolAddress((void**)&pf1,  w_ff1);
    cudaGetSymbolAddress((void**)&pf2,  w_ff2);
    cudaGetSymbolAddress((void**)&pte,  w_te);

    // --- fork side stream for background weight conversion
    cudaStream_t s2;
    cudaStreamCreateWithFlags(&s2, cudaStreamNonBlocking);
    cudaEvent_t evFork, evQ, evO, evF1, evF2, evTE;
    cudaEventCreateWithFlags(&evFork, cudaEventDisableTiming);
    cudaEventCreateWithFlags(&evQ,    cudaEventDisableTiming);
    cudaEventCreateWithFlags(&evO,    cudaEventDisableTiming);
    cudaEventCreateWithFlags(&evF1,   cudaEventDisableTiming);
    cudaEventCreateWithFlags(&evF2,   cudaEventDisableTiming);
    cudaEventCreateWithFlags(&evTE,   cudaEventDisableTiming);

    cudaEventRecord(evFork, 0);
    cudaStreamWaitEvent(s2, evFork, 0);

    cvt_on(s2, qkv_w, pwq, (size_t)L * 3 * D * D);  cudaEventRecord(evQ,  s2);
    cvt_on(s2, out_w, pwo, (size_t)L * D * D);      cudaEventRecord(evO,  s2);
    cvt_on(s2, ff1_w, pf1, (size_t)L * 4 * D * D);  cudaEventRecord(evF1, s2);
    cvt_on(s2, ff2_w, pf2, (size_t)L * 4 * D * D);  cudaEventRecord(evF2, s2);
    cvt_on(s2, wte,   pte, (size_t)V * D);          cudaEventRecord(evTE, s2);

    pe_kernel<<<B, T>>>(idx);
    embed_kernel<<<(NTOK * D / 4) / 256, 256>>>(idx, vis, wte, wpe);

    for (int l = 0; l < L; l++) {
        const __half* qw  = pwq + (size_t)l * 3 * D * D;
        const __half* ow  = pwo + (size_t)l * D * D;
        const __half* f1w = pf1 + (size_t)l * 4 * D * D;
        const __half* f2w = pf2 + (size_t)l * 4 * D * D;
        const float* qb  = qkv_b + (size_t)l * 3 * D;
        const float* ob  = out_b + (size_t)l * D;
        const float* f1b = ff1_b + (size_t)l * 4 * D;
        const float* f2b = ff2_b + (size_t)l * D;

        ln_split_kernel<<<NTOK, 256>>>(px, ln1_w + l * D, ln1_b + l * D, pah, pal);
        if (l == 0) cudaStreamWaitEvent(0, evQ, 0);
        gemm_mma<true, false, false, true, true><<<dim3(NTOK / 128, 3 * D / 128), 256, GEMM_SMEM>>>(
            pah, pal, qw, qb, nullptr, nullptr, pqh, pql, 3 * D, D);

        flash_kernel<<<dim3(S / 128, B * H), 256, FLASH_SMEM>>>(pqh, pql, pah, pal);

        if (l == 0) cudaStreamWaitEvent(0, evO, 0);
        gemm_mma<true, false, true, false, true><<<dim3(NTOK / 128, D / 128), 256, GEMM_SMEM>>>(
            pah, pal, ow, ob, px, px, nullptr, nullptr, D, D);

        ln_split_kernel<<<NTOK, 256>>>(px, ln2_w + l * D, ln2_b + l * D, pah, pal);
        if (l == 0) cudaStreamWaitEvent(0, evF1, 0);
        gemm_mma<true, true, false, true, true><<<dim3(NTOK / 128, 4 * D / 128), 256, GEMM_SMEM>>>(
            pah, pal, f1w, f1b, nullptr, nullptr, pa2h, pa2l, 4 * D, D);

        if (l == 0) cudaStreamWaitEvent(0, evF2, 0);
        gemm_mma<true, false, true, false, true><<<dim3(NTOK / 128, D / 128), 256, GEMM_SMEM>>>(
            pa2h, pa2l, f2w, f2b, px, px, nullptr, nullptr, D, 4 * D);
    }

    ln_split_kernel<<<NTOK, 256>>>(px, lnf_w, lnf_b, pah, pal);
    cudaStreamWaitEvent(0, evTE, 0);
    gemm_mma<false, false, false, false, false><<<dim3(NTOK / 128, V / 128), 256, GEMM_SMEM>>>(
        pah, nullptr, pte, nullptr, nullptr, logits, nullptr, nullptr, V, D);
}

// round 16
// speedup vs baseline: 1.0423x; 1.0423x over previous
#include <cuda_runtime.h>
#include <cuda_bf16.h>
#include <cuda_fp16.h>
#include <math.h>
#include <stdint.h>
#include <stddef.h>

// Problem constants
constexpr int B   = 2;
constexpr int T   = 768;
constexpr int KV  = 256;
constexpr int S   = 1024;
constexpr int D   = 1024;
constexpr int H   = 16;
constexpr int DH  = 64;
constexpr int L   = 6;
constexpr int V   = 32000;
constexpr int NTOK = B * S;
constexpr int PHYS_TOK = 5;

// ---------------- fp32 scratch ----------------------------------------------
__device__ float g_x  [NTOK * D];
__device__ int   g_pe [B];

// ---------------- fp16 storage ------------------------------------------------
__device__ __half w_qkv[L*3*D*D];
__device__ __half w_out[L*D*D];
__device__ __half w_ff1[L*4*D*D];
__device__ __half w_ff2[L*4*D*D];
__device__ __half w_te [(size_t)V*D];
__device__ __half a_h [NTOK*D],   a_l [NTOK*D];
__device__ __half a2_h[NTOK*4*D], a2_l[NTOK*4*D];
__device__ __half qkv_h[NTOK*3*D], qkv_l[NTOK*3*D];

// ============================ PTX helpers ====================================
__device__ __forceinline__ uint32_t smem_to_u32(const void* p) {
    uint32_t a;
    asm("{ .reg .u64 t; cvta.to.shared.u64 t, %1; cvt.u32.u64 %0, t; }" : "=r"(a) : "l"(p));
    return a;
}
__device__ __forceinline__ void ldmx4(uint32_t* r, uint32_t addr) {
    asm volatile("ldmatrix.sync.aligned.m8n8.x4.shared.b16 {%0,%1,%2,%3}, [%4];"
        : "=r"(r[0]), "=r"(r[1]), "=r"(r[2]), "=r"(r[3]) : "r"(addr));
}
__device__ __forceinline__ void ldmx4t(uint32_t* r, uint32_t addr) {
    asm volatile("ldmatrix.sync.aligned.m8n8.x4.trans.shared.b16 {%0,%1,%2,%3}, [%4];"
        : "=r"(r[0]), "=r"(r[1]), "=r"(r[2]), "=r"(r[3]) : "r"(addr));
}
__device__ __forceinline__ void mma_fp16(float* c, const uint32_t* a, const uint32_t* b) {
    asm volatile("mma.sync.aligned.m16n8k16.row.col.f32.f16.f16.f32 "
        "{%0,%1,%2,%3}, {%4,%5,%6,%7}, {%8,%9}, {%0,%1,%2,%3};"
        : "+f"(c[0]), "+f"(c[1]), "+f"(c[2]), "+f"(c[3])
        : "r"(a[0]), "r"(a[1]), "r"(a[2]), "r"(a[3]), "r"(b[0]), "r"(b[1]));
}
__device__ __forceinline__ void cp16(uint32_t dst, const void* src) {
    asm volatile("cp.async.cg.shared.global [%0], [%1], 16;" :: "r"(dst), "l"(src));
}
__device__ __forceinline__ void cp_commit() {
    asm volatile("cp.async.commit_group;" ::: "memory");
}
template<int N>
__device__ __forceinline__ void cp_wait() {
    asm volatile("cp.async.wait_group %0;" :: "n"(N) : "memory");
}
__device__ __forceinline__ uint32_t pack_h2(float a, float b) {
    __half2 t;
    t.x = __float2half_rn(a); t.y = __float2half_rn(b);
    return *(uint32_t*)&t;
}

// ---------------- small kernels ----------------------------------------------
// parallel first-PHYS_TOK scan: grid B, block T threads
__global__ void pe_kernel(const int* __restrict__ idx) {
    __shared__ int mn;
    if (threadIdx.x == 0) mn = T;
    __syncthreads();
    int b = blockIdx.x;
    if (idx[b * T + threadIdx.x] == PHYS_TOK) atomicMin(&mn, (int)threadIdx.x);
    __syncthreads();
    if (threadIdx.x == 0) g_pe[b] = (mn < T) ? mn + 1 : 0;
}

// vectorized embedding splice (4 elems per thread)
__global__ void embed_kernel(const int* __restrict__ idx, const float* __restrict__ vis,
                             const float* __restrict__ wte, const float* __restrict__ wpe) {
    int i4 = blockIdx.x * blockDim.x + threadIdx.x;
    int e = i4 * 4;
    int d = e & (D - 1);
    int p = (e / D) & (S - 1);
    int b = e / (D * S);
    int pe = g_pe[b];
    float4 v;
    if (p >= pe && p < pe + KV) {
        v = *(const float4*)(vis + ((size_t)b * KV + (p - pe)) * D + d);
    } else {
        int ti = (p < pe) ? p : (p - KV);
        ti = min(max(ti, 0), T - 1);
        v = *(const float4*)(wte + (size_t)idx[b * T + ti] * D + d);
    }
    float4 w = *(const float4*)(wpe + (size_t)p * D + d);
    v.x += w.x; v.y += w.y; v.z += w.z; v.w += w.w;
    *(float4*)(g_x + e) = v;
}

// LayerNorm with fused fp16 hi/lo split output (vectorized)
__global__ void ln_split_kernel(const float* __restrict__ in,
                                const float* __restrict__ w, const float* __restrict__ b,
                                __half* __restrict__ oh, __half* __restrict__ ol) {
    int row = blockIdx.x;
    const float* x = in + (size_t)row * D;
    int j0 = threadIdx.x * 4;
    float4 xv = *(const float4*)(x + j0);
    float s  = xv.x + xv.y + xv.z + xv.w;
    float s2 = xv.x * xv.x + xv.y * xv.y + xv.z * xv.z + xv.w * xv.w;
#pragma unroll
    for (int o = 16; o; o >>= 1) { s += __shfl_xor_sync(~0u, s, o); s2 += __shfl_xor_sync(~0u, s2, o); }
    __shared__ float sh1[8], sh2[8];
    int wid = threadIdx.x >> 5, lid = threadIdx.x & 31;
    if (lid == 0) { sh1[wid] = s; sh2[wid] = s2; }
    __syncthreads();
    s = 0.f; s2 = 0.f;
#pragma unroll
    for (int wg = 0; wg < 8; wg++) { s += sh1[wg]; s2 += sh2[wg]; }
    float mean = s * (1.f / D);
    float var  = s2 * (1.f / D) - mean * mean;
    float inv  = rsqrtf(var + 1e-5f);
    float4 wv = *(const float4*)(w + j0);
    float4 bv = *(const float4*)(b + j0);
    float y0 = (xv.x - mean) * inv * wv.x + bv.x;
    float y1 = (xv.y - mean) * inv * wv.y + bv.y;
    float y2 = (xv.z - mean) * inv * wv.z + bv.z;
    float y3 = (xv.w - mean) * inv * wv.w + bv.w;
    __half2 h01, h23, l01, l23;
    h01.x = __float2half_rn(y0); h01.y = __float2half_rn(y1);
    h23.x = __float2half_rn(y2); h23.y = __float2half_rn(y3);
    l01.x = __float2half_rn(y0 - __half2float(h01.x));
    l01.y = __float2half_rn(y1 - __half2float(h01.y));
    l23.x = __float2half_rn(y2 - __half2float(h23.x));
    l23.y = __float2half_rn(y3 - __half2float(h23.y));
    *(__half2*)(oh + (size_t)row * D + j0)     = h01;
    *(__half2*)(oh + (size_t)row * D + j0 + 2) = h23;
    *(__half2*)(ol + (size_t)row * D + j0)     = l01;
    *(__half2*)(ol + (size_t)row * D + j0 + 2) = l23;
}

// fp32 -> fp16 weight convert (full grid — fast, critical-path friendly)
__global__ void cvt_kernel(const float4* __restrict__ x, __half2* __restrict__ o, int n4) {
    int i = blockIdx.x * blockDim.x + threadIdx.x;
    if (i >= n4) return;
    float4 v = x[i];
    __half2 h0, h1;
    h0.x = __float2half_rn(v.x); h0.y = __float2half_rn(v.y);
    h1.x = __float2half_rn(v.z); h1.y = __float2half_rn(v.w);
    o[i * 2]     = h0;
    o[i * 2 + 1] = h1;
}

__device__ __forceinline__ float gelu_exact(float x) {
    return 0.5f * x * (1.f + erff(x * 0.70710678118654752f));
}

// ================= fp16 GEMM (split A optional, single W), 3-stage pipeline ==
constexpr int LDSROW = 40;
constexpr int TILE_BYTES = 128 * LDSROW * 2;
constexpr int BUF_BYTES  = 3 * TILE_BYTES;
constexpr int GEMM_SMEM  = 3 * BUF_BYTES;

__device__ __forceinline__ void cp_tile(uint32_t dst, const __half* __restrict__ src,
                                        int Kd, int k0) {
    int tid = threadIdx.x;
#pragma unroll
    for (int i = 0; i < 2; i++) {
        int v = tid * 2 + i;
        int row = v >> 2, seg = v & 3;
        cp16(dst + (uint32_t)(row * LDSROW + seg * 8) * 2,
             src + (size_t)row * Kd + k0 + seg * 8);
    }
}

template<bool BIAS, bool GELU, bool RES, bool SPLIT, bool TWOTERM>
__global__ __launch_bounds__(256, 2)
void gemm_mma(const __half* __restrict__ A1, const __half* __restrict__ A0,
              const __half* __restrict__ W,
              const float* __restrict__ bias, const float* __restrict__ res,
              float* __restrict__ C, __half* __restrict__ Ch,
              __half* __restrict__ Cl, int N, int Kd) {
    extern __shared__ char smem[];
    const uint32_t sbase = smem_to_u32(smem);

    const int tid  = threadIdx.x;
    const int lane = tid & 31;
    const int wid  = tid >> 5;
    const int wm   = wid >> 1;
    const int wn   = wid & 1;
    const int bm   = blockIdx.x * 128;
    const int bn   = blockIdx.y * 128;

    const __half* pA1 = A1 + (size_t)bm * Kd;
    const __half* pA0 = A0 + (size_t)bm * Kd;
    const __half* pW  = W  + (size_t)bn * Kd;

    const uint32_t frag_lane = (uint32_t)((lane & 15) * LDSROW + (lane >> 4) * 8);
    const int nch = Kd / 32;

    auto issue = [&](int ch) {
        uint32_t b = sbase + (uint32_t)(ch % 3) * BUF_BYTES;
        int k0 = ch * 32;
        cp_tile(b,                  pA1, Kd, k0);
        if (TWOTERM) cp_tile(b + TILE_BYTES, pA0, Kd, k0);
        cp_tile(b + 2 * TILE_BYTES, pW,  Kd, k0);
        cp_commit();
    };

    float c[2][8][4];
#pragma unroll
    for (int mt = 0; mt < 2; mt++)
#pragma unroll
        for (int nt = 0; nt < 8; nt++)
#pragma unroll
            for (int q = 0; q < 4; q++) c[mt][nt][q] = 0.f;

    issue(0);
    issue(1);

    for (int ch = 0; ch < nch; ch++) {
        if (ch < nch - 1) cp_wait<1>(); else cp_wait<0>();
        __syncthreads();
        if (ch + 2 < nch) issue(ch + 2);
        uint32_t b = sbase + (uint32_t)(ch % 3) * BUF_BYTES;
#pragma unroll
        for (int ks = 0; ks < 2; ks++) {
            uint32_t a1f[2][4], a0f[2][4];
#pragma unroll
            for (int mt = 0; mt < 2; mt++) {
                uint32_t off = ((uint32_t)((wm * 32 + mt * 16) * LDSROW + ks * 16) + frag_lane) * 2;
                ldmx4(a1f[mt], b + off);
                if (TWOTERM) ldmx4(a0f[mt], b + TILE_BYTES + off);
            }
            uint32_t wf[8][2];
#pragma unroll
            for (int jj = 0; jj < 4; jj++) {
                uint32_t off = ((uint32_t)((wn * 64 + jj * 16) * LDSROW + ks * 16) + frag_lane) * 2;
                uint32_t t[4];
                ldmx4(t, b + 2 * TILE_BYTES + off);
                wf[jj * 2][0]     = t[0]; wf[jj * 2 + 1][0] = t[1];
                wf[jj * 2][1]     = t[2]; wf[jj * 2 + 1][1] = t[3];
            }
#pragma unroll
            for (int mt = 0; mt < 2; mt++)
#pragma unroll
                for (int nt = 0; nt < 8; nt++) {
                    mma_fp16(c[mt][nt], a1f[mt], wf[nt]);
                    if (TWOTERM) mma_fp16(c[mt][nt], a0f[mt], wf[nt]);
                }
        }
    }

    const int row0 = bm + wm * 32;
    const int col0 = bn + wn * 64;
#pragma unroll
    for (int mt = 0; mt < 2; mt++) {
#pragma unroll
        for (int nt = 0; nt < 8; nt++) {
            int r  = row0 + mt * 16 + (lane >> 2);
            int cl = col0 + nt * 8 + (lane & 3) * 2;
#pragma unroll
            for (int half = 0; half < 2; half++) {
                int rr = r + half * 8;
                float v0 = c[mt][nt][half * 2];
                float v1 = c[mt][nt][half * 2 + 1];
                if (BIAS) { v0 += bias[cl]; v1 += bias[cl + 1]; }
                if (GELU) { v0 = gelu_exact(v0); v1 = gelu_exact(v1); }
                if (RES) {
                    const float* rp = res + (size_t)rr * N + cl;
                    v0 += rp[0]; v1 += rp[1];
                }
                if (SPLIT) {
                    __half2 hh, ll;
                    hh.x = __float2half_rn(v0);
                    hh.y = __float2half_rn(v1);
                    ll.x = __float2half_rn(v0 - __half2float(hh.x));
                    ll.y = __float2half_rn(v1 - __half2float(hh.y));
                    *(__half2*)(Ch + (size_t)rr * N + cl) = hh;
                    *(__half2*)(Cl + (size_t)rr * N + cl) = ll;
                } else {
                    *(float2*)(C + (size_t)rr * N + cl) = make_float2(v0, v1);
                }
            }
        }
    }
}

// ================= fused flash attention (fp16 split, 3-stage pipeline) ======
constexpr int QROW = 72;
constexpr int KVBUF_ELEM = 4 * 64 * QROW;
constexpr int FLASH_SMEM = (2 * 128 * QROW + 3 * KVBUF_ELEM) * 2;

__global__ __launch_bounds__(256, 1)
void flash_kernel(const __half* __restrict__ qg_h, const __half* __restrict__ qg_l,
                  __half* __restrict__ oh, __half* __restrict__ ol) {
    extern __shared__ char smemc[];
    __half* smem = (__half*)smemc;
    __half* sQh = smem;
    __half* sQl = sQh + 128 * QROW;
    __half* sKV = sQl + 128 * QROW;

    const int tid = threadIdx.x, lane = tid & 31, w = tid >> 5;
    const int bh = blockIdx.y, b = bh >> 4, h = bh & 15;
    const int qBase = blockIdx.x * 128;
    const int pe = g_pe[b], ve = pe + KV;

    const uint32_t aQh = smem_to_u32(sQh), aQl = smem_to_u32(sQl);
    const uint32_t aKV = smem_to_u32(sKV);

    const int kEnd = min(S, max(qBase + 128, ve));
    const int nk = (kEnd + 63) >> 6;

    auto issue_kv = [&](int t) {
        uint32_t base = aKV + (uint32_t)(t % 3) * (KVBUF_ELEM * 2);
        int k0 = t * 64;
#pragma unroll
        for (int it = 0; it < 8; it++) {
            int c = it * 256 + tid;
            int comp = c >> 9;
            int r    = (c >> 3) & 63;
            int seg  = c & 7;
            const __half* src = ((comp & 1) ? qg_l : qg_h)
                + (size_t)(b * S + k0 + r) * (3 * D) + ((comp < 2) ? D : 2 * D) + h * DH + seg * 8;
            cp16(base + (uint32_t)(comp * 64 * QROW + r * QROW + seg * 8) * 2, src);
        }
        cp_commit();
    };

#pragma unroll
    for (int it = 0; it < 8; it++) {
        int c = it * 256 + tid;
        int hl  = c >> 10;
        int r   = (c >> 3) & 127;
        int seg = c & 7;
        const __half* src = (hl ? qg_l : qg_h)
            + (size_t)(b * S + qBase + r) * (3 * D) + h * DH + seg * 8;
        cp16((hl ? aQl : aQh) + (uint32_t)(r * QROW + seg * 8) * 2, src);
    }
    issue_kv(0);
    issue_kv(1);

    const uint32_t flq = (uint32_t)((lane & 15) * QROW + (lane >> 4) * 8);
    const uint32_t flv = (uint32_t)(((lane & 7) + ((lane >> 3) & 1) * 8) * QROW + (lane >> 4) * 8);

    uint32_t qh[4][4], ql[4][4];
    float acc[8][4];
#pragma unroll
    for (int nt = 0; nt < 8; nt++)
#pragma unroll
        for (int e = 0; e < 4; e++) acc[nt][e] = 0.f;
    float m0 = -1e30f, m1 = -1e30f, l0 = 0.f, l1 = 0.f;
    const int qr = qBase + w * 16 + (lane >> 2);

    for (int i = 0; i < nk; i++) {
        if (i < nk - 1) cp_wait<1>(); else cp_wait<0>();
        __syncthreads();
        if (i + 2 < nk) issue_kv(i + 2);

        if (i == 0) {
#pragma unroll
            for (int kk = 0; kk < 4; kk++) {
                uint32_t off = ((uint32_t)(w * 16 * QROW + kk * 16) + flq) * 2;
                ldmx4(qh[kk], aQh + off);
                ldmx4(ql[kk], aQl + off);
            }
        }

        uint32_t base = aKV + (uint32_t)(i % 3) * (KVBUF_ELEM * 2);
        const uint32_t bKh = base;
        const uint32_t bKl = base + 64 * QROW * 2;
        const uint32_t bVh = base + 2 * 64 * QROW * 2;
        const uint32_t bVl = base + 3 * 64 * QROW * 2;
        int k0 = i * 64;

        float c[8][4];
#pragma unroll
        for (int nt = 0; nt < 8; nt++)
#pragma unroll
            for (int e = 0; e < 4; e++) c[nt][e] = 0.f;
#pragma unroll
        for (int kk = 0; kk < 4; kk++) {
#pragma unroll
            for (int jj = 0; jj < 4; jj++) {
                uint32_t off = ((uint32_t)((jj * 16) * QROW + kk * 16) + flq) * 2;
                uint32_t th[4], tl[4];
                ldmx4(th, bKh + off);
                ldmx4(tl, bKl + off);
                uint32_t kh0[2] = { th[0], th[2] }, kh1[2] = { th[1], th[3] };
                uint32_t kl0[2] = { tl[0], tl[2] }, kl1[2] = { tl[1], tl[3] };
                mma_fp16(c[jj * 2],     qh[kk], kh0);
                mma_fp16(c[jj * 2],     qh[kk], kl0);
                mma_fp16(c[jj * 2],     ql[kk], kh0);
                mma_fp16(c[jj * 2 + 1], qh[kk], kh1);
                mma_fp16(c[jj * 2 + 1], qh[kk], kl1);
                mma_fp16(c[jj * 2 + 1], ql[kk], kh1);
            }
        }

        float mx0 = -1e30f, mx1 = -1e30f;
#pragma unroll
        for (int nt = 0; nt < 8; nt++) {
            int kc = k0 + nt * 8 + (lane & 3) * 2;
#pragma unroll
            for (int e = 0; e < 4; e++) {
                int q = qr + ((e >= 2) ? 8 : 0);
                int k = kc + (e & 1);
                bool allowed = (q < pe && k < pe) ||
                               (q >= pe && q < ve && k < ve) ||
                               (q >= ve && k <= q);
                float s = allowed ? c[nt][e] * 0.125f : -1e9f;
                c[nt][e] = s;
                if (e < 2) mx0 = fmaxf(mx0, s); else mx1 = fmaxf(mx1, s);
            }
        }
        mx0 = fmaxf(mx0, __shfl_xor_sync(~0u, mx0, 1));
        mx0 = fmaxf(mx0, __shfl_xor_sync(~0u, mx0, 2));
        mx1 = fmaxf(mx1, __shfl_xor_sync(~0u, mx1, 1));
        mx1 = fmaxf(mx1, __shfl_xor_sync(~0u, mx1, 2));

        float mn0 = fmaxf(m0, mx0), mn1 = fmaxf(m1, mx1);
        float al0 = __expf(m0 - mn0), al1 = __expf(m1 - mn1);
        m0 = mn0; m1 = mn1;

        uint32_t ph[4][4], pl[4][4];
        float rs0 = 0.f, rs1 = 0.f;
#pragma unroll
        for (int nt = 0; nt < 8; nt++) {
            float p0 = __expf(c[nt][0] - m0);
            float p1 = __expf(c[nt][1] - m0);
            float p2 = __expf(c[nt][2] - m1);
            float p3 = __expf(c[nt][3] - m1);
            rs0 += p0 + p1; rs1 += p2 + p3;
            __half h0 = __float2half_rn(p0), h1 = __float2half_rn(p1);
            __half h2 = __float2half_rn(p2), h3 = __float2half_rn(p3);
            int ck = nt >> 1, ps = (nt & 1) * 2;
            __half2 t;
            t.x = h0; t.y = h1; ph[ck][ps]     = *(uint32_t*)&t;
            t.x = h2; t.y = h3; ph[ck][ps + 1] = *(uint32_t*)&t;
            pl[ck][ps]     = pack_h2(p0 - __half2float(h0), p1 - __half2float(h1));
            pl[ck][ps + 1] = pack_h2(p2 - __half2float(h2), p3 - __half2float(h3));
        }
        rs0 += __shfl_xor_sync(~0u, rs0, 1); rs0 += __shfl_xor_sync(~0u, rs0, 2);
        rs1 += __shfl_xor_sync(~0u, rs1, 1); rs1 += __shfl_xor_sync(~0u, rs1, 2);
        l0 = l0 * al0 + rs0;
        l1 = l1 * al1 + rs1;

#pragma unroll
        for (int nt = 0; nt < 8; nt++) {
            acc[nt][0] *= al0; acc[nt][1] *= al0;
            acc[nt][2] *= al1; acc[nt][3] *= al1;
        }

#pragma unroll
        for (int kk = 0; kk < 4; kk++) {
#pragma unroll
            for (int jj = 0; jj < 4; jj++) {
                uint32_t off = ((uint32_t)(kk * 16 * QROW + jj * 16) + flv) * 2;
                uint32_t th[4], tl[4];
                ldmx4t(th, bVh + off);
                ldmx4t(tl, bVl + off);
                uint32_t vh0[2] = { th[0], th[1] }, vh1[2] = { th[2], th[3] };
                uint32_t vl0[2] = { tl[0], tl[1] }, vl1[2] = { tl[2], tl[3] };
                mma_fp16(acc[jj * 2],     ph[kk], vh0);
                mma_fp16(acc[jj * 2],     ph[kk], vl0);
                mma_fp16(acc[jj * 2],     pl[kk], vh0);
                mma_fp16(acc[jj * 2 + 1], ph[kk], vh1);
                mma_fp16(acc[jj * 2 + 1], ph[kk], vl1);
                mma_fp16(acc[jj * 2 + 1], pl[kk], vh1);
            }
        }
    }

    const float il0 = 1.f / l0, il1 = 1.f / l1;
#pragma unroll
    for (int nt = 0; nt < 8; nt++) {
        int dcol = h * DH + nt * 8 + (lane & 3) * 2;
        size_t o0 = (size_t)(b * S + qr) * D + dcol;
        size_t o1 = (size_t)(b * S + qr + 8) * D + dcol;
        float v0 = acc[nt][0] * il0, v1 = acc[nt][1] * il0;
        float v2 = acc[nt][2] * il1, v3 = acc[nt][3] * il1;
        __half2 hh, ll;
        hh.x = __float2half_rn(v0); hh.y = __float2half_rn(v1);
        ll.x = __float2half_rn(v0 - __half2float(hh.x));
        ll.y = __float2half_rn(v1 - __half2float(hh.y));
        *(__half2*)(oh + o0) = hh;
        *(__half2*)(ol + o0) = ll;
        hh.x = __float2half_rn(v2); hh.y = __float2half_rn(v3);
        ll.x = __float2half_rn(v2 - __half2float(hh.x));
        ll.y = __float2half_rn(v3 - __half2float(hh.y));
        *(__half2*)(oh + o1) = hh;
        *(__half2*)(ol + o1) = ll;
    }
}

// ---------------- host: launch sequence --------------------------------------
static inline void cvt_on(cudaStream_t s, const float* x, __half* o, size_t n) {
    int n4 = (int)(n / 4);
    cvt_kernel<<<(n4 + 255) / 256, 256, 0, s>>>((const float4*)x, (__half2*)o, n4);
}

extern "C" void kernel_launch(void* const* d_in, const int* in_sizes, int n_in,
                              void* d_out, int out_size) {
    const int*   idx    = (const int*)  d_in[0];
    const float* vis    = (const float*)d_in[1];
    const float* wte    = (const float*)d_in[2];
    const float* wpe    = (const float*)d_in[3];
    const float* qkv_w  = (const float*)d_in[4];
    const float* qkv_b  = (const float*)d_in[5];
    const float* out_w  = (const float*)d_in[6];
    const float* out_b  = (const float*)d_in[7];
    const float* ln1_w  = (const float*)d_in[8];
    const float* ln1_b  = (const float*)d_in[9];
    const float* ln2_w  = (const float*)d_in[10];
    const float* ln2_b  = (const float*)d_in[11];
    const float* ff1_w  = (const float*)d_in[12];
    const float* ff1_b  = (const float*)d_in[13];
    const float* ff2_w  = (const float*)d_in[14];
    const float* ff2_b  = (const float*)d_in[15];
    const float* lnf_w  = (const float*)d_in[16];
    const float* lnf_b  = (const float*)d_in[17];
    float* logits = (float*)d_out;

    cudaFuncSetAttribute(gemm_mma<true,  false, false, true,  true >, cudaFuncAttributeMaxDynamicSharedMemorySize, GEMM_SMEM);
    cudaFuncSetAttribute(gemm_mma<true,  false, true,  false, true >, cudaFuncAttributeMaxDynamicSharedMemorySize, GEMM_SMEM);
    cudaFuncSetAttribute(gemm_mma<true,  true,  false, true,  true >, cudaFuncAttributeMaxDynamicSharedMemorySize, GEMM_SMEM);
    cudaFuncSetAttribute(gemm_mma<false, false, false, false, false>, cudaFuncAttributeMaxDynamicSharedMemorySize, GEMM_SMEM);
    cudaFuncSetAttribute(flash_kernel, cudaFuncAttributeMaxDynamicSharedMemorySize, FLASH_SMEM);

    float* px;
    cudaGetSymbolAddress((void**)&px, g_x);
    __half *pah, *pal, *pa2h, *pa2l, *pqh, *pql, *pwq, *pwo, *pf1, *pf2, *pte;
    cudaGetSymbolAddress((void**)&pah,  a_h);
    cudaGetSymbolAddress((void**)&pal,  a_l);
    cudaGetSymbolAddress((void**)&pa2h, a2_h);
    cudaGetSymbolAddress((void**)&pa2l, a2_l);
    cudaGetSymbolAddress((void**)&pqh,  qkv_h);
    cudaGetSymbolAddress((void**)&pql,  qkv_l);
    cudaGetSymbolAddress((void**)&pwq,  w_qkv);
    cudaGetSymbolAddress((void**)&pwo,  w_out);
    cudaGetSymbolAddress((void**)&pf1,  w_ff1);
    cudaGetSymbolAddress((void**)&pf2,  w_ff2);
    cudaGetSymbolAddress((void**)&pte,  w_te);

    // --- fork side stream for weight conversion (full-grid kernels, R14 style)
    cudaStream_t s2;
    cudaStreamCreateWithFlags(&s2, cudaStreamNonBlocking);
    cudaEvent_t evFork, evQ, evO, evF1, evF2, evTE;
    cudaEventCreateWithFlags(&evFork, cudaEventDisableTiming);
    cudaEventCreateWithFlags(&evQ,    cudaEventDisableTiming);
    cudaEventCreateWithFlags(&evO,    cudaEventDisableTiming);
    cudaEventCreateWithFlags(&evF1,   cudaEventDisableTiming);
    cudaEventCreateWithFlags(&evF2,   cudaEventDisableTiming);
    cudaEventCreateWithFlags(&evTE,   cudaEventDisableTiming);

    cudaEventRecord(evFork, 0);
    cudaStreamWaitEvent(s2, evFork, 0);

    cvt_on(s2, qkv_w, pwq, (size_t)L * 3 * D * D);  cudaEventRecord(evQ,  s2);
    cvt_on(s2, out_w, pwo, (size_t)L * D * D);      cudaEventRecord(evO,  s2);
    cvt_on(s2, ff1_w, pf1, (size_t)L * 4 * D * D);  cudaEventRecord(evF1, s2);
    cvt_on(s2, ff2_w, pf2, (size_t)L * 4 * D * D);  cudaEventRecord(evF2, s2);
    cvt_on(s2, wte,   pte, (size_t)V * D);          cudaEventRecord(evTE, s2);

    pe_kernel<<<B, T>>>(idx);
    embed_kernel<<<(NTOK * D / 4) / 256, 256>>>(idx, vis, wte, wpe);

    for (int l = 0; l < L; l++) {
        const __half* qw  = pwq + (size_t)l * 3 * D * D;
        const __half* ow  = pwo + (size_t)l * D * D;
        const __half* f1w = pf1 + (size_t)l * 4 * D * D;
        const __half* f2w = pf2 + (size_t)l * 4 * D * D;
        const float* qb  = qkv_b + (size_t)l * 3 * D;
        const float* ob  = out_b + (size_t)l * D;
        const float* f1b = ff1_b + (size_t)l * 4 * D;
        const float* f2b = ff2_b + (size_t)l * D;

        ln_split_kernel<<<NTOK, 256>>>(px, ln1_w + l * D, ln1_b + l * D, pah, pal);
        if (l == 0) cudaStreamWaitEvent(0, evQ, 0);
        gemm_mma<true, false, false, true, true><<<dim3(NTOK / 128, 3 * D / 128), 256, GEMM_SMEM>>>(
            pah, pal, qw, qb, nullptr, nullptr, pqh, pql, 3 * D, D);

        flash_kernel<<<dim3(S / 128, B * H), 256, FLASH_SMEM>>>(pqh, pql, pah, pal);

        if (l == 0) cudaStreamWaitEvent(0, evO, 0);
        gemm_mma<true, false, true, false, true><<<dim3(NTOK / 128, D / 128), 256, GEMM_SMEM>>>(
            pah, pal, ow, ob, px, px, nullptr, nullptr, D, D);

        ln_split_kernel<<<NTOK, 256>>>(px, ln2_w + l * D, ln2_b + l * D, pah, pal);
        if (l == 0) cudaStreamWaitEvent(0, evF1, 0);
        gemm_mma<true, true, false, true, true><<<dim3(NTOK / 128, 4 * D / 128), 256, GEMM_SMEM>>>(
            pah, pal, f1w, f1b, nullptr, nullptr, pa2h, pa2l, 4 * D, D);

        if (l == 0) cudaStreamWaitEvent(0, evF2, 0);
        gemm_mma<true, false, true, false, true><<<dim3(NTOK / 128, D / 128), 256, GEMM_SMEM>>>(
            pa2h, pa2l, f2w, f2b, px, px, nullptr, nullptr, D, 4 * D);
    }

    ln_split_kernel<<<NTOK, 256>>>(px, lnf_w, lnf_b, pah, pal);
    cudaStreamWaitEvent(0, evTE, 0);
    gemm_mma<false, false, false, false, false><<<dim3(NTOK / 128, V / 128), 256, GEMM_SMEM>>>(
        pah, nullptr, pte, nullptr, nullptr, logits, nullptr, nullptr, V, D);
}